// round 1
// baseline (speedup 1.0000x reference)
#include <cuda_runtime.h>
#include <math.h>

// ---------------- problem constants ----------------
#define BSZ   32
#define DMODEL 512
#define SEQL  128
#define NTOK  (BSZ*SEQL)     // 4096
#define NHEAD 8
#define DKH   64
#define HID   2048
#define NLAYER 8

// ---------------- scratch (device globals; no allocation allowed) ----------
__device__ float g_p  [2*BSZ*DMODEL*64];   // pooled  [src][b][c][s]
__device__ float g_hpp[2*BSZ*DMODEL*64];   // hp*p    [src][b][c][s]
__device__ float g_M  [4*BSZ*8*64];        // sigmoid masks [v][b][o][s]
__device__ float g_x  [NTOK*DMODEL];
__device__ float g_ln [NTOK*DMODEL];
__device__ float g_q  [NTOK*DMODEL];
__device__ float g_k  [NTOK*DMODEL];
__device__ float g_v  [NTOK*DMODEL];
__device__ float g_att[BSZ*NHEAD*SEQL*SEQL];
__device__ float g_o  [NTOK*DMODEL];
__device__ float g_h  [NTOK*HID];

__constant__ float COS8[8] = {1.f,-0.70710678118654752f,0.f,0.70710678118654752f,
                              -1.f,0.70710678118654752f,0.f,-0.70710678118654752f};
__constant__ float SIN8[8] = {0.f,0.70710678118654752f,-1.f,0.70710678118654752f,
                              0.f,-0.70710678118654752f,1.f,-0.70710678118654752f};

// ---------------- 1) avgpool 4x4 + single-bin highpass, fused -------------
// hp = x - Re(F[3,3] * e^{i theta})/64, theta = (3pi/4)(m+n).
__global__ void pool_hp_kernel(const float* __restrict__ rgb, const float* __restrict__ ir) {
    __shared__ float sp[64];
    __shared__ float red[4];
    int c = blockIdx.x, b = blockIdx.y, src = blockIdx.z;
    int tid = threadIdx.x;  // 256
    const float* in = (src == 0 ? rgb : ir) + ((size_t)(b*DMODEL + c))*1024;
    if (tid < 64) sp[tid] = 0.f;
    __syncthreads();
    float4 v = ((const float4*)in)[tid];
    atomicAdd(&sp[(tid>>5)*8 + (tid&7)], v.x+v.y+v.z+v.w);
    __syncthreads();
    size_t base = ((size_t)((src*BSZ + b)*DMODEL + c))*64;
    float x = 0.f, ct = 0.f, st = 0.f;
    if (tid < 64) {
        x = sp[tid]*(1.f/16.f);
        g_p[base + tid] = x;
        int idx = (3*((tid>>3) + (tid&7))) & 7;
        ct = COS8[idx]; st = SIN8[idx];
    }
    float xc = x*ct, xs = x*st;
    if (tid < 64) {
        #pragma unroll
        for (int off = 16; off; off >>= 1) {
            xc += __shfl_down_sync(0xffffffffu, xc, off);
            xs += __shfl_down_sync(0xffffffffu, xs, off);
        }
        if ((tid&31) == 0) { red[(tid>>5)*2] = xc; red[(tid>>5)*2+1] = xs; }
    }
    __syncthreads();
    if (tid < 64) {
        float Fr = red[0] + red[2];
        float Fi = -(red[1] + red[3]);
        float hp = x - (Fr*ct - Fi*st)*(1.f/64.f);
        g_hpp[base + tid] = hp * x;
    }
}

// ---------------- 2) conv1 (512->8) + sigmoid, 4 variants ------------------
__global__ void conv1_kernel(const float* __restrict__ w) { // grid (32,4), 512 thr
    __shared__ float sw[8*512];
    int b = blockIdx.x, v = blockIdx.y;
    int tid = threadIdx.x;
    for (int i = tid; i < 4096; i += 512) sw[i] = w[i];
    const float* X = (v < 2 ? g_p : g_hpp) + ((size_t)(((v&1)*BSZ + b)*DMODEL))*64;
    __syncthreads();
    int o = tid >> 6, s = tid & 63;
    float acc = 0.f;
    for (int cc = 0; cc < 512; cc++) acc += sw[o*512 + cc] * X[cc*64 + s];
    g_M[((size_t)(v*BSZ + b)*8 + o)*64 + s] = 1.f/(1.f + __expf(-acc));
}

// ---------------- 3) pattern loss ------------------------------------------
__global__ void loss_kernel(float* __restrict__ out_loss) { // 1 block, 512 thr
    __shared__ float scol[512];
    __shared__ float swarp[16];
    int tid = threadIdx.x;
    int col = tid & 63, grp = tid >> 6;
    float s = 0.f, sq = 0.f;
    for (int v = 0; v < 4; v++) {
        int nrows = (v < 2) ? 256 : 32;  // hp variants: only b<4 (first 32 rows)
        for (int r = grp; r < nrows; r += 8) {
            float m = g_M[(size_t)(v*256 + r)*64 + col];
            s += m; sq += m*m;
        }
    }
    scol[tid] = s;
    #pragma unroll
    for (int off = 16; off; off >>= 1) sq += __shfl_down_sync(0xffffffffu, sq, off);
    if ((tid&31) == 0) swarp[tid>>5] = sq;
    __syncthreads();
    if (tid < 64) {
        float st = 0.f;
        #pragma unroll
        for (int g = 0; g < 8; g++) st += scol[g*64 + tid];
        scol[tid] = st*st;
    }
    __syncthreads();
    if (tid == 0) {
        float ss = 0.f;  for (int j = 0; j < 64; j++) ss  += scol[j];
        float sqa = 0.f; for (int wgi = 0; wgi < 16; wgi++) sqa += swarp[wgi];
        out_loss[0] = (ss - sqa)*0.5f/(576.f*575.f);
    }
}

// ---------------- 4) tokens: x = pos + (conv2(M) * p)^T --------------------
__global__ void buildx_kernel(const float* __restrict__ pos, const float* __restrict__ c2w) {
    __shared__ float sw[4096];
    __shared__ float sm[8];
    int t = blockIdx.x, b = blockIdx.y;
    int d = threadIdx.x;  // 512
    for (int i = d; i < 4096; i += 512) sw[i] = c2w[i];
    int which = t >> 6, s = t & 63;
    if (d < 8) sm[d] = g_M[((size_t)(which*BSZ + b)*8 + d)*64 + s];
    __syncthreads();
    float acc = 0.f;
    #pragma unroll
    for (int o = 0; o < 8; o++) acc += sw[d*8 + o] * sm[o];
    float p = g_p[((size_t)((which*BSZ + b)*DMODEL + d))*64 + s];
    g_x[(size_t)(b*SEQL + t)*DMODEL + d] = pos[t*DMODEL + d] + acc*p;
}

// ---------------- LayerNorm (rows=4096, width=512) -------------------------
__global__ void ln_kernel(const float* __restrict__ x, float* __restrict__ y,
                          const float* __restrict__ w, const float* __restrict__ bsh) {
    __shared__ float red[4];
    int row = blockIdx.x, tid = threadIdx.x;  // 128
    float4 v = ((const float4*)(x + (size_t)row*512))[tid];
    float sum = v.x+v.y+v.z+v.w;
    #pragma unroll
    for (int off = 16; off; off >>= 1) sum += __shfl_down_sync(0xffffffffu, sum, off);
    if ((tid&31) == 0) red[tid>>5] = sum;
    __syncthreads();
    float mean = (red[0]+red[1]+red[2]+red[3])*(1.f/512.f);
    float dx = v.x-mean, dy = v.y-mean, dz = v.z-mean, dw = v.w-mean;
    float sq = dx*dx+dy*dy+dz*dz+dw*dw;
    __syncthreads();
    #pragma unroll
    for (int off = 16; off; off >>= 1) sq += __shfl_down_sync(0xffffffffu, sq, off);
    if ((tid&31) == 0) red[tid>>5] = sq;
    __syncthreads();
    float inv = rsqrtf((red[0]+red[1]+red[2]+red[3])*(1.f/512.f) + 1e-5f);
    float4 wv = ((const float4*)w)[tid];
    float4 bv = ((const float4*)bsh)[tid];
    float4 o;
    o.x = dx*inv*wv.x + bv.x; o.y = dy*inv*wv.y + bv.y;
    o.z = dz*inv*wv.z + bv.z; o.w = dw*inv*wv.w + bv.w;
    ((float4*)(y + (size_t)row*512))[tid] = o;
}

// ---------------- GEMM: C = act(A@B + bias) [+ resid] ----------------------
// A[M,K] row-major, B[K,N] row-major. BM=128,BN=64,BK=16, 256 thr, 8x4/thr.
// ACT: 0 = bias, 1 = bias+gelu(exact), 2 = bias+residual.
template<int ACT>
__global__ void __launch_bounds__(256) gemm_kernel(
    const float* __restrict__ A, const float* __restrict__ B,
    const float* __restrict__ bias, const float* __restrict__ resid,
    float* __restrict__ C, int M, int N, int K)
{
    __shared__ float As[16][128];
    __shared__ float Bs[16][64];
    int tid = threadIdx.x;
    int bm = blockIdx.y*128, bn = blockIdx.x*64;
    int tm = (tid>>4)*8, tn = (tid&15)*4;
    float acc[8][4] = {};
    for (int k0 = 0; k0 < K; k0 += 16) {
        #pragma unroll
        for (int i = 0; i < 2; i++) {
            int idx = tid + i*256;
            int row = idx >> 2, c4 = (idx & 3)*4;
            float4 a = *(const float4*)(A + (size_t)(bm+row)*K + k0 + c4);
            As[c4  ][row] = a.x; As[c4+1][row] = a.y;
            As[c4+2][row] = a.z; As[c4+3][row] = a.w;
        }
        {
            int row = tid >> 4, c4 = (tid & 15)*4;
            *(float4*)&Bs[row][c4] = *(const float4*)(B + (size_t)(k0+row)*N + bn + c4);
        }
        __syncthreads();
        #pragma unroll
        for (int k = 0; k < 16; k++) {
            float a[8], bb[4];
            #pragma unroll
            for (int i = 0; i < 8; i++) a[i] = As[k][tm+i];
            #pragma unroll
            for (int j = 0; j < 4; j++) bb[j] = Bs[k][tn+j];
            #pragma unroll
            for (int i = 0; i < 8; i++)
                #pragma unroll
                for (int j = 0; j < 4; j++) acc[i][j] += a[i]*bb[j];
        }
        __syncthreads();
    }
    float4 b4 = *(const float4*)(bias + bn + tn);
    #pragma unroll
    for (int i = 0; i < 8; i++) {
        size_t off = (size_t)(bm+tm+i)*N + bn + tn;
        float4 r = make_float4(acc[i][0]+b4.x, acc[i][1]+b4.y,
                               acc[i][2]+b4.z, acc[i][3]+b4.w);
        if (ACT == 1) {
            r.x *= normcdff(r.x); r.y *= normcdff(r.y);
            r.z *= normcdff(r.z); r.w *= normcdff(r.w);
        }
        if (ACT == 2) {
            float4 rs = *(const float4*)(resid + off);
            r.x += rs.x; r.y += rs.y; r.z += rs.z; r.w += rs.w;
        }
        *(float4*)(C + off) = r;
    }
}

// ---------------- attention scores: S = Q K^T / 8 per (b,h) ----------------
__global__ void __launch_bounds__(256) score_kernel() {
    __shared__ float Qs[128][33];
    __shared__ float Kts[32][132];
    int bh = blockIdx.x, b = bh >> 3, h = bh & 7;
    int tid = threadIdx.x;
    const float* qp = g_q + (size_t)b*65536 + h*64;
    const float* kp = g_k + (size_t)b*65536 + h*64;
    int tq = (tid>>4)*8, tk = (tid&15)*8;
    float acc[8][8] = {};
    for (int half = 0; half < 2; half++) {
        #pragma unroll
        for (int i = 0; i < 4; i++) {
            int idx = tid + i*256;
            int row = idx >> 3, c4 = (idx & 7)*4;
            float4 q4 = *(const float4*)(qp + (size_t)row*512 + half*32 + c4);
            Qs[row][c4] = q4.x; Qs[row][c4+1] = q4.y; Qs[row][c4+2] = q4.z; Qs[row][c4+3] = q4.w;
            float4 k4 = *(const float4*)(kp + (size_t)row*512 + half*32 + c4);
            Kts[c4][row] = k4.x; Kts[c4+1][row] = k4.y; Kts[c4+2][row] = k4.z; Kts[c4+3][row] = k4.w;
        }
        __syncthreads();
        #pragma unroll 4
        for (int d = 0; d < 32; d++) {
            float a[8], bb[8];
            #pragma unroll
            for (int i = 0; i < 8; i++) a[i] = Qs[tq+i][d];
            #pragma unroll
            for (int j = 0; j < 8; j++) bb[j] = Kts[d][tk+j];
            #pragma unroll
            for (int i = 0; i < 8; i++)
                #pragma unroll
                for (int j = 0; j < 8; j++) acc[i][j] += a[i]*bb[j];
        }
        __syncthreads();
    }
    float* sp = g_att + (size_t)bh*16384;
    #pragma unroll
    for (int i = 0; i < 8; i++)
        #pragma unroll
        for (int j = 0; j < 8; j++)
            sp[(size_t)(tq+i)*128 + tk + j] = acc[i][j]*0.125f;
}

// ---------------- softmax over k (width 128), warp per row -----------------
__global__ void softmax_kernel() {
    int row = blockIdx.x*8 + (threadIdx.x>>5);
    int lane = threadIdx.x & 31;
    float* p = g_att + (size_t)row*128 + lane*4;
    float4 v = *(const float4*)p;
    float mx = fmaxf(fmaxf(v.x, v.y), fmaxf(v.z, v.w));
    #pragma unroll
    for (int off = 16; off; off >>= 1) mx = fmaxf(mx, __shfl_xor_sync(0xffffffffu, mx, off));
    v.x = __expf(v.x-mx); v.y = __expf(v.y-mx); v.z = __expf(v.z-mx); v.w = __expf(v.w-mx);
    float s = v.x+v.y+v.z+v.w;
    #pragma unroll
    for (int off = 16; off; off >>= 1) s += __shfl_xor_sync(0xffffffffu, s, off);
    float inv = 1.f/s;
    v.x *= inv; v.y *= inv; v.z *= inv; v.w *= inv;
    *(float4*)p = v;
}

// ---------------- O = att @ V per (b,h) -------------------------------------
__global__ void __launch_bounds__(256) av_kernel() {
    __shared__ float Vs[128][68];
    __shared__ float Att[128][17];
    int bh = blockIdx.x, b = bh >> 3, h = bh & 7;
    int tid = threadIdx.x;
    const float* vp = g_v + (size_t)b*65536 + h*64;
    #pragma unroll
    for (int i = 0; i < 8; i++) {
        int idx = tid + i*256;
        int row = idx >> 4, c4 = (idx & 15)*4;
        *(float4*)&Vs[row][c4] = *(const float4*)(vp + (size_t)row*512 + c4);
    }
    const float* ap = g_att + (size_t)bh*16384;
    int tq = (tid>>4)*8, td = (tid&15)*4;
    float acc[8][4] = {};
    for (int kt = 0; kt < 8; kt++) {
        __syncthreads();
        #pragma unroll
        for (int i = 0; i < 2; i++) {
            int idx = tid + i*256;
            int row = idx >> 2, c4 = (idx & 3)*4;
            float4 a4 = *(const float4*)(ap + (size_t)row*128 + kt*16 + c4);
            Att[row][c4] = a4.x; Att[row][c4+1] = a4.y; Att[row][c4+2] = a4.z; Att[row][c4+3] = a4.w;
        }
        __syncthreads();
        #pragma unroll 4
        for (int k = 0; k < 16; k++) {
            float a[8], bb[4];
            #pragma unroll
            for (int i = 0; i < 8; i++) a[i] = Att[tq+i][k];
            #pragma unroll
            for (int j = 0; j < 4; j++) bb[j] = Vs[kt*16+k][td+j];
            #pragma unroll
            for (int i = 0; i < 8; i++)
                #pragma unroll
                for (int j = 0; j < 4; j++) acc[i][j] += a[i]*bb[j];
        }
    }
    float* op = g_o + (size_t)b*65536 + h*64;
    #pragma unroll
    for (int i = 0; i < 8; i++)
        *(float4*)(op + (size_t)(tq+i)*512 + td) =
            make_float4(acc[i][0], acc[i][1], acc[i][2], acc[i][3]);
}

// ---------------- bilinear upsample 8x8 -> 32x32 (half-pixel, clamp) -------
__global__ void upsample_kernel(float* __restrict__ out) { // grid (512,32,2), 256 thr
    __shared__ float g[64];
    int d = blockIdx.x, b = blockIdx.y, which = blockIdx.z;
    int tid = threadIdx.x;
    if (tid < 64)
        g[tid] = g_ln[(size_t)(b*SEQL + which*64 + tid)*512 + d];
    __syncthreads();
    float* op = out + (size_t)which*(BSZ*512*1024) + ((size_t)(b*512 + d))*1024;
    #pragma unroll
    for (int r = 0; r < 4; r++) {
        int pix = tid + r*256;
        int oy = pix >> 5, ox = pix & 31;
        float cy = (oy + 0.5f)*0.25f - 0.5f;
        float cx = (ox + 0.5f)*0.25f - 0.5f;
        int y0 = (int)floorf(cy); float wy = cy - y0;
        int x0 = (int)floorf(cx); float wx = cx - x0;
        int y1 = min(y0+1, 7); y0 = max(y0, 0);
        int x1 = min(x0+1, 7); x0 = max(x0, 0);
        float v00 = g[y0*8+x0], v01 = g[y0*8+x1], v10 = g[y1*8+x0], v11 = g[y1*8+x1];
        op[pix] = (1.f-wy)*((1.f-wx)*v00 + wx*v01) + wy*((1.f-wx)*v10 + wx*v11);
    }
}

// ---------------- launcher --------------------------------------------------
extern "C" void kernel_launch(void* const* d_in, const int* in_sizes, int n_in,
                              void* d_out, int out_size) {
    const float* rgb  = (const float*)d_in[0];
    const float* ir   = (const float*)d_in[1];
    const float* pos  = (const float*)d_in[2];
    const float* c1w  = (const float*)d_in[3];
    const float* c2w  = (const float*)d_in[4];
    const float* ln1w = (const float*)d_in[5];
    const float* ln1b = (const float*)d_in[6];
    const float* Wq   = (const float*)d_in[7];
    const float* bq   = (const float*)d_in[8];
    const float* Wk   = (const float*)d_in[9];
    const float* bk   = (const float*)d_in[10];
    const float* Wv   = (const float*)d_in[11];
    const float* bv   = (const float*)d_in[12];
    const float* Wo   = (const float*)d_in[13];
    const float* bo   = (const float*)d_in[14];
    const float* ln2w = (const float*)d_in[15];
    const float* ln2b = (const float*)d_in[16];
    const float* W1   = (const float*)d_in[17];
    const float* b1   = (const float*)d_in[18];
    const float* W2   = (const float*)d_in[19];
    const float* b2   = (const float*)d_in[20];
    const float* lnfw = (const float*)d_in[21];
    const float* lnfb = (const float*)d_in[22];
    float* out = (float*)d_out;

    float *p_x, *p_ln, *p_q, *p_k, *p_v, *p_o, *p_h;
    cudaGetSymbolAddress((void**)&p_x,  g_x);
    cudaGetSymbolAddress((void**)&p_ln, g_ln);
    cudaGetSymbolAddress((void**)&p_q,  g_q);
    cudaGetSymbolAddress((void**)&p_k,  g_k);
    cudaGetSymbolAddress((void**)&p_v,  g_v);
    cudaGetSymbolAddress((void**)&p_o,  g_o);
    cudaGetSymbolAddress((void**)&p_h,  g_h);

    pool_hp_kernel<<<dim3(DMODEL, BSZ, 2), 256>>>(rgb, ir);
    conv1_kernel<<<dim3(BSZ, 4), 512>>>(c1w);
    loss_kernel<<<1, 512>>>(out + (size_t)2*BSZ*512*1024);
    buildx_kernel<<<dim3(SEQL, BSZ), 512>>>(pos, c2w);

    dim3 g512(512/64, NTOK/128);   // (8,32)
    dim3 g2048(2048/64, NTOK/128); // (32,32)

    for (int l = 0; l < NLAYER; l++) {
        size_t wOff = (size_t)l*512*512, bOff = (size_t)l*512;
        size_t w1Off = (size_t)l*512*2048, b1Off = (size_t)l*2048;
        ln_kernel<<<NTOK, 128>>>(p_x, p_ln, ln1w + bOff, ln1b + bOff);
        gemm_kernel<0><<<g512, 256>>>(p_ln, Wq + wOff, bq + bOff, nullptr, p_q, NTOK, 512, 512);
        gemm_kernel<0><<<g512, 256>>>(p_ln, Wk + wOff, bk + bOff, nullptr, p_k, NTOK, 512, 512);
        gemm_kernel<0><<<g512, 256>>>(p_ln, Wv + wOff, bv + bOff, nullptr, p_v, NTOK, 512, 512);
        score_kernel<<<BSZ*NHEAD, 256>>>();
        softmax_kernel<<<BSZ*NHEAD*SEQL/8, 256>>>();
        av_kernel<<<BSZ*NHEAD, 256>>>();
        gemm_kernel<2><<<g512, 256>>>(p_o, Wo + wOff, bo + bOff, p_x, p_x, NTOK, 512, 512);
        ln_kernel<<<NTOK, 128>>>(p_x, p_ln, ln2w + bOff, ln2b + bOff);
        gemm_kernel<1><<<g2048, 256>>>(p_ln, W1 + w1Off, b1 + b1Off, nullptr, p_h, NTOK, 2048, 512);
        gemm_kernel<2><<<g512, 256>>>(p_h, W2 + w1Off, b2 + bOff, p_x, p_x, NTOK, 512, 2048);
    }
    ln_kernel<<<NTOK, 128>>>(p_x, p_ln, lnfw, lnfb);
    upsample_kernel<<<dim3(512, BSZ, 2), 256>>>(out);
}

// round 2
// speedup vs baseline: 2.3070x; 2.3070x over previous
#include <cuda_runtime.h>
#include <math.h>
#include <stdint.h>

// ---------------- problem constants ----------------
#define BSZ   32
#define DMODEL 512
#define SEQL  128
#define NTOK  (BSZ*SEQL)     // 4096
#define NHEAD 8
#define HID   2048
#define NLAYER 8

// ---------------- scratch ----------------
__device__ float g_p  [2*BSZ*DMODEL*64];
__device__ float g_hpp[2*BSZ*DMODEL*64];
__device__ float g_M  [4*BSZ*8*64];
__device__ float g_x  [NTOK*DMODEL];
__device__ float g_ln [NTOK*DMODEL];
__device__ float g_q  [NTOK*DMODEL];
__device__ float g_k  [NTOK*DMODEL];
__device__ float g_v  [NTOK*DMODEL];
__device__ float g_o  [NTOK*DMODEL];
__device__ float g_h  [NTOK*HID];

__constant__ float COS8[8] = {1.f,-0.70710678118654752f,0.f,0.70710678118654752f,
                              -1.f,0.70710678118654752f,0.f,-0.70710678118654752f};
__constant__ float SIN8[8] = {0.f,0.70710678118654752f,-1.f,0.70710678118654752f,
                              0.f,-0.70710678118654752f,1.f,-0.70710678118654752f};

// ---------------- tf32 helpers ----------------
__device__ __forceinline__ uint32_t f2tf(float f) {
    uint32_t r;
    asm("cvt.rna.tf32.f32 %0, %1;" : "=r"(r) : "f"(f));
    return r;
}
__device__ __forceinline__ uint4 cvt4(float4 v) {
    uint4 u; u.x = f2tf(v.x); u.y = f2tf(v.y); u.z = f2tf(v.z); u.w = f2tf(v.w);
    return u;
}
__device__ __forceinline__ void mma_tf32(float* c, uint32_t a0, uint32_t a1,
                                         uint32_t a2, uint32_t a3,
                                         uint32_t b0, uint32_t b1) {
    asm volatile(
        "mma.sync.aligned.m16n8k8.row.col.f32.tf32.tf32.f32 "
        "{%0,%1,%2,%3},{%4,%5,%6,%7},{%8,%9},{%0,%1,%2,%3};"
        : "+f"(c[0]), "+f"(c[1]), "+f"(c[2]), "+f"(c[3])
        : "r"(a0), "r"(a1), "r"(a2), "r"(a3), "r"(b0), "r"(b1));
}

// ---------------- 1) avgpool 4x4 + single-bin highpass -------------
__global__ void pool_hp_kernel(const float* __restrict__ rgb, const float* __restrict__ ir) {
    __shared__ float sp[64];
    __shared__ float red[4];
    int c = blockIdx.x, b = blockIdx.y, src = blockIdx.z;
    int tid = threadIdx.x;
    const float* in = (src == 0 ? rgb : ir) + ((size_t)(b*DMODEL + c))*1024;
    if (tid < 64) sp[tid] = 0.f;
    __syncthreads();
    float4 v = ((const float4*)in)[tid];
    atomicAdd(&sp[(tid>>5)*8 + (tid&7)], v.x+v.y+v.z+v.w);
    __syncthreads();
    size_t base = ((size_t)((src*BSZ + b)*DMODEL + c))*64;
    float x = 0.f, ct = 0.f, st = 0.f;
    if (tid < 64) {
        x = sp[tid]*(1.f/16.f);
        g_p[base + tid] = x;
        int idx = (3*((tid>>3) + (tid&7))) & 7;
        ct = COS8[idx]; st = SIN8[idx];
    }
    float xc = x*ct, xs = x*st;
    if (tid < 64) {
        #pragma unroll
        for (int off = 16; off; off >>= 1) {
            xc += __shfl_down_sync(0xffffffffu, xc, off);
            xs += __shfl_down_sync(0xffffffffu, xs, off);
        }
        if ((tid&31) == 0) { red[(tid>>5)*2] = xc; red[(tid>>5)*2+1] = xs; }
    }
    __syncthreads();
    if (tid < 64) {
        float Fr = red[0] + red[2];
        float Fi = -(red[1] + red[3]);
        float hp = x - (Fr*ct - Fi*st)*(1.f/64.f);
        g_hpp[base + tid] = hp * x;
    }
}

// ---------------- 2) conv1 (512->8) + sigmoid ------------------
__global__ void conv1_kernel(const float* __restrict__ w) {
    __shared__ float sw[8*512];
    int b = blockIdx.x, v = blockIdx.y;
    int tid = threadIdx.x;
    for (int i = tid; i < 4096; i += 512) sw[i] = w[i];
    const float* X = (v < 2 ? g_p : g_hpp) + ((size_t)(((v&1)*BSZ + b)*DMODEL))*64;
    __syncthreads();
    int o = tid >> 6, s = tid & 63;
    float acc = 0.f;
    for (int cc = 0; cc < 512; cc++) acc += sw[o*512 + cc] * X[cc*64 + s];
    g_M[((size_t)(v*BSZ + b)*8 + o)*64 + s] = 1.f/(1.f + __expf(-acc));
}

// ---------------- 3) pattern loss ------------------------------------------
__global__ void loss_kernel(float* __restrict__ out_loss) {
    __shared__ float scol[512];
    __shared__ float swarp[16];
    int tid = threadIdx.x;
    int col = tid & 63, grp = tid >> 6;
    float s = 0.f, sq = 0.f;
    for (int v = 0; v < 4; v++) {
        int nrows = (v < 2) ? 256 : 32;
        for (int r = grp; r < nrows; r += 8) {
            float m = g_M[(size_t)(v*256 + r)*64 + col];
            s += m; sq += m*m;
        }
    }
    scol[tid] = s;
    #pragma unroll
    for (int off = 16; off; off >>= 1) sq += __shfl_down_sync(0xffffffffu, sq, off);
    if ((tid&31) == 0) swarp[tid>>5] = sq;
    __syncthreads();
    if (tid < 64) {
        float st = 0.f;
        #pragma unroll
        for (int g = 0; g < 8; g++) st += scol[g*64 + tid];
        scol[tid] = st*st;
    }
    __syncthreads();
    if (tid == 0) {
        float ss = 0.f;  for (int j = 0; j < 64; j++) ss  += scol[j];
        float sqa = 0.f; for (int wgi = 0; wgi < 16; wgi++) sqa += swarp[wgi];
        out_loss[0] = (ss - sqa)*0.5f/(576.f*575.f);
    }
}

// ---------------- 4) tokens -------------------------------------------------
__global__ void buildx_kernel(const float* __restrict__ pos, const float* __restrict__ c2w) {
    __shared__ float sw[4096];
    __shared__ float sm[8];
    int t = blockIdx.x, b = blockIdx.y;
    int d = threadIdx.x;
    for (int i = d; i < 4096; i += 512) sw[i] = c2w[i];
    int which = t >> 6, s = t & 63;
    if (d < 8) sm[d] = g_M[((size_t)(which*BSZ + b)*8 + d)*64 + s];
    __syncthreads();
    float acc = 0.f;
    #pragma unroll
    for (int o = 0; o < 8; o++) acc += sw[d*8 + o] * sm[o];
    float p = g_p[((size_t)((which*BSZ + b)*DMODEL + d))*64 + s];
    g_x[(size_t)(b*SEQL + t)*DMODEL + d] = pos[t*DMODEL + d] + acc*p;
}

// ---------------- LayerNorm -------------------------------------------------
__global__ void ln_kernel(const float* __restrict__ x, float* __restrict__ y,
                          const float* __restrict__ w, const float* __restrict__ bsh) {
    __shared__ float red[4];
    int row = blockIdx.x, tid = threadIdx.x;
    float4 v = ((const float4*)(x + (size_t)row*512))[tid];
    float sum = v.x+v.y+v.z+v.w;
    #pragma unroll
    for (int off = 16; off; off >>= 1) sum += __shfl_down_sync(0xffffffffu, sum, off);
    if ((tid&31) == 0) red[tid>>5] = sum;
    __syncthreads();
    float mean = (red[0]+red[1]+red[2]+red[3])*(1.f/512.f);
    float dx = v.x-mean, dy = v.y-mean, dz = v.z-mean, dw = v.w-mean;
    float sq = dx*dx+dy*dy+dz*dz+dw*dw;
    __syncthreads();
    #pragma unroll
    for (int off = 16; off; off >>= 1) sq += __shfl_down_sync(0xffffffffu, sq, off);
    if ((tid&31) == 0) red[tid>>5] = sq;
    __syncthreads();
    float inv = rsqrtf((red[0]+red[1]+red[2]+red[3])*(1.f/512.f) + 1e-5f);
    float4 wv = ((const float4*)w)[tid];
    float4 bv = ((const float4*)bsh)[tid];
    float4 o;
    o.x = dx*inv*wv.x + bv.x; o.y = dy*inv*wv.y + bv.y;
    o.z = dz*inv*wv.z + bv.z; o.w = dw*inv*wv.w + bv.w;
    ((float4*)(y + (size_t)row*512))[tid] = o;
}

// ---------------- tf32 GEMM: C = act(A@B + bias) [+resid] ------------------
// A[M,K] rm, B[K,N] rm. CTA 128x128, 8 warps x (32x64). ACT: 0 bias,1 gelu,2 resid.
template<int ACT>
__global__ void __launch_bounds__(256) gemm_tf32(
    const float* __restrict__ A, const float* __restrict__ B,
    const float* __restrict__ bias, const float* __restrict__ resid,
    float* __restrict__ C, int M, int N, int K)
{
    __shared__ uint32_t As[2][128*20];   // stride 20: conflict-free frags
    __shared__ uint32_t Bs[2][16*136];   // stride 136
    int tid = threadIdx.x;
    int bm = blockIdx.y*128, bn = blockIdx.x*128;
    int warp = tid>>5, lane = tid&31;
    int wm = (warp&3)*32, wn = (warp>>2)*64;
    int lr = lane>>2, lc = lane&3;

    float4 pa[2], pb[2];
    float acc[2][8][4] = {};

    // prefetch k0=0
    #pragma unroll
    for (int i = 0; i < 2; i++) {
        int idx = tid + i*256;
        pa[i] = *(const float4*)(A + (size_t)(bm + (idx>>2))*K + (idx&3)*4);
        pb[i] = *(const float4*)(B + (size_t)(idx>>5)*N + bn + (idx&31)*4);
    }
    #pragma unroll
    for (int i = 0; i < 2; i++) {
        int idx = tid + i*256;
        *(uint4*)&As[0][(idx>>2)*20 + (idx&3)*4] = cvt4(pa[i]);
        *(uint4*)&Bs[0][(idx>>5)*136 + (idx&31)*4] = cvt4(pb[i]);
    }
    __syncthreads();

    int KT = K >> 4;
    for (int kt = 0; kt < KT; kt++) {
        int s = kt & 1;
        if (kt + 1 < KT) {
            int k0 = (kt+1) << 4;
            #pragma unroll
            for (int i = 0; i < 2; i++) {
                int idx = tid + i*256;
                pa[i] = *(const float4*)(A + (size_t)(bm + (idx>>2))*K + k0 + (idx&3)*4);
                pb[i] = *(const float4*)(B + (size_t)(k0 + (idx>>5))*N + bn + (idx&31)*4);
            }
        }
        #pragma unroll
        for (int kk = 0; kk < 2; kk++) {
            uint32_t a[2][4], b[8][2];
            #pragma unroll
            for (int mt = 0; mt < 2; mt++) {
                int r0 = wm + mt*16 + lr;
                int cc = kk*8 + lc;
                a[mt][0] = As[s][r0*20 + cc];
                a[mt][1] = As[s][(r0+8)*20 + cc];
                a[mt][2] = As[s][r0*20 + cc + 4];
                a[mt][3] = As[s][(r0+8)*20 + cc + 4];
            }
            #pragma unroll
            for (int nt = 0; nt < 8; nt++) {
                int cn = wn + nt*8 + lr;
                b[nt][0] = Bs[s][(kk*8+lc)*136 + cn];
                b[nt][1] = Bs[s][(kk*8+lc+4)*136 + cn];
            }
            #pragma unroll
            for (int mt = 0; mt < 2; mt++)
                #pragma unroll
                for (int nt = 0; nt < 8; nt++)
                    mma_tf32(acc[mt][nt], a[mt][0], a[mt][1], a[mt][2], a[mt][3],
                             b[nt][0], b[nt][1]);
        }
        if (kt + 1 < KT) {
            #pragma unroll
            for (int i = 0; i < 2; i++) {
                int idx = tid + i*256;
                *(uint4*)&As[1-s][(idx>>2)*20 + (idx&3)*4] = cvt4(pa[i]);
                *(uint4*)&Bs[1-s][(idx>>5)*136 + (idx&31)*4] = cvt4(pb[i]);
            }
        }
        __syncthreads();
    }

    #pragma unroll
    for (int mt = 0; mt < 2; mt++) {
        int row0 = bm + wm + mt*16 + lr;
        #pragma unroll
        for (int nt = 0; nt < 8; nt++) {
            int col = bn + wn + nt*8 + 2*lc;
            float2 bb = *(const float2*)(bias + col);
            float v0 = acc[mt][nt][0] + bb.x, v1 = acc[mt][nt][1] + bb.y;
            float v2 = acc[mt][nt][2] + bb.x, v3 = acc[mt][nt][3] + bb.y;
            if (ACT == 1) {
                v0 *= normcdff(v0); v1 *= normcdff(v1);
                v2 *= normcdff(v2); v3 *= normcdff(v3);
            }
            size_t o0 = (size_t)row0*N + col;
            size_t o1 = (size_t)(row0+8)*N + col;
            if (ACT == 2) {
                float2 r0 = *(const float2*)(resid + o0);
                float2 r1 = *(const float2*)(resid + o1);
                v0 += r0.x; v1 += r0.y; v2 += r1.x; v3 += r1.y;
            }
            *(float2*)(C + o0) = make_float2(v0, v1);
            *(float2*)(C + o1) = make_float2(v2, v3);
        }
    }
}

// ---------------- fused attention per (b,h): S=QK^T/8, softmax, O=PV -------
__global__ void __launch_bounds__(256) attn_kernel() {
    extern __shared__ uint32_t smw[];
    uint32_t* Vs = smw;                 // [128][72]
    uint32_t* Qs = smw + 128*72;        // [128][68]
    uint32_t* Ks = Qs + 128*68;         // [128][68]
    uint32_t* Ps = Qs;                  // alias [128][132] (16896 <= 17408)

    int bh = blockIdx.x, b = bh >> 3, h = bh & 7;
    int tid = threadIdx.x, warp = tid>>5, lane = tid&31;
    int lr = lane>>2, lc = lane&3;
    const float* qp = g_q + (size_t)b*65536 + h*64;
    const float* kp = g_k + (size_t)b*65536 + h*64;
    const float* vp = g_v + (size_t)b*65536 + h*64;

    #pragma unroll
    for (int i = 0; i < 8; i++) {
        int idx = tid + i*256;       // 2048 float4 per tensor
        int s = idx >> 4, c4 = (idx & 15)*4;
        *(uint4*)&Qs[s*68 + c4] = cvt4(*(const float4*)(qp + (size_t)s*512 + c4));
        *(uint4*)&Ks[s*68 + c4] = cvt4(*(const float4*)(kp + (size_t)s*512 + c4));
        *(uint4*)&Vs[s*72 + c4] = cvt4(*(const float4*)(vp + (size_t)s*512 + c4));
    }
    __syncthreads();

    // score: each warp owns 16 q-rows
    int qr = warp*16 + lr;
    float accs[16][4] = {};
    #pragma unroll
    for (int kk = 0; kk < 8; kk++) {
        int cc = kk*8 + lc;
        uint32_t a0 = Qs[qr*68 + cc],     a1 = Qs[(qr+8)*68 + cc];
        uint32_t a2 = Qs[qr*68 + cc + 4], a3 = Qs[(qr+8)*68 + cc + 4];
        #pragma unroll
        for (int nt = 0; nt < 16; nt++) {
            int kn = nt*8 + lr;
            uint32_t b0 = Ks[kn*68 + cc];
            uint32_t b1 = Ks[kn*68 + cc + 4];
            mma_tf32(accs[nt], a0, a1, a2, a3, b0, b1);
        }
    }
    // softmax (rows qr via c0/c1, qr+8 via c2/c3); cols spread over lc group
    float m0 = -1e30f, m1 = -1e30f;
    #pragma unroll
    for (int nt = 0; nt < 16; nt++) {
        #pragma unroll
        for (int j = 0; j < 4; j++) accs[nt][j] *= 0.125f;
        m0 = fmaxf(m0, fmaxf(accs[nt][0], accs[nt][1]));
        m1 = fmaxf(m1, fmaxf(accs[nt][2], accs[nt][3]));
    }
    m0 = fmaxf(m0, __shfl_xor_sync(0xffffffffu, m0, 1));
    m0 = fmaxf(m0, __shfl_xor_sync(0xffffffffu, m0, 2));
    m1 = fmaxf(m1, __shfl_xor_sync(0xffffffffu, m1, 1));
    m1 = fmaxf(m1, __shfl_xor_sync(0xffffffffu, m1, 2));
    float s0 = 0.f, s1 = 0.f;
    #pragma unroll
    for (int nt = 0; nt < 16; nt++) {
        accs[nt][0] = __expf(accs[nt][0] - m0);
        accs[nt][1] = __expf(accs[nt][1] - m0);
        accs[nt][2] = __expf(accs[nt][2] - m1);
        accs[nt][3] = __expf(accs[nt][3] - m1);
        s0 += accs[nt][0] + accs[nt][1];
        s1 += accs[nt][2] + accs[nt][3];
    }
    s0 += __shfl_xor_sync(0xffffffffu, s0, 1);
    s0 += __shfl_xor_sync(0xffffffffu, s0, 2);
    s1 += __shfl_xor_sync(0xffffffffu, s1, 1);
    s1 += __shfl_xor_sync(0xffffffffu, s1, 2);
    float i0 = 1.f/s0, i1 = 1.f/s1;

    __syncthreads();  // all warps done reading Qs/Ks before P overwrites
    #pragma unroll
    for (int nt = 0; nt < 16; nt++) {
        int c = nt*8 + 2*lc;
        Ps[qr*132 + c]       = f2tf(accs[nt][0]*i0);
        Ps[qr*132 + c + 1]   = f2tf(accs[nt][1]*i0);
        Ps[(qr+8)*132 + c]   = f2tf(accs[nt][2]*i1);
        Ps[(qr+8)*132 + c+1] = f2tf(accs[nt][3]*i1);
    }
    __syncthreads();

    // O = P @ V : M=128 (16 rows/warp), N=64, K=128
    float acco[8][4] = {};
    #pragma unroll
    for (int kk = 0; kk < 16; kk++) {
        int cc = kk*8 + lc;
        uint32_t a0 = Ps[qr*132 + cc],     a1 = Ps[(qr+8)*132 + cc];
        uint32_t a2 = Ps[qr*132 + cc + 4], a3 = Ps[(qr+8)*132 + cc + 4];
        #pragma unroll
        for (int nt = 0; nt < 8; nt++) {
            int dn = nt*8 + lr;
            uint32_t b0 = Vs[cc*72 + dn];
            uint32_t b1 = Vs[(cc+4)*72 + dn];
            mma_tf32(acco[nt], a0, a1, a2, a3, b0, b1);
        }
    }
    float* op = g_o + (size_t)b*65536 + h*64;
    #pragma unroll
    for (int nt = 0; nt < 8; nt++) {
        int col = nt*8 + 2*lc;
        *(float2*)(op + (size_t)qr*512 + col)     = make_float2(acco[nt][0], acco[nt][1]);
        *(float2*)(op + (size_t)(qr+8)*512 + col) = make_float2(acco[nt][2], acco[nt][3]);
    }
}

// ---------------- bilinear upsample 8x8 -> 32x32 ----------------------------
__global__ void upsample_kernel(float* __restrict__ out) {
    __shared__ float g[64];
    int d = blockIdx.x, b = blockIdx.y, which = blockIdx.z;
    int tid = threadIdx.x;
    if (tid < 64)
        g[tid] = g_ln[(size_t)(b*SEQL + which*64 + tid)*512 + d];
    __syncthreads();
    float* op = out + (size_t)which*(BSZ*512*1024) + ((size_t)(b*512 + d))*1024;
    #pragma unroll
    for (int r = 0; r < 4; r++) {
        int pix = tid + r*256;
        int oy = pix >> 5, ox = pix & 31;
        float cy = (oy + 0.5f)*0.25f - 0.5f;
        float cx = (ox + 0.5f)*0.25f - 0.5f;
        int y0 = (int)floorf(cy); float wy = cy - y0;
        int x0 = (int)floorf(cx); float wx = cx - x0;
        int y1 = min(y0+1, 7); y0 = max(y0, 0);
        int x1 = min(x0+1, 7); x0 = max(x0, 0);
        float v00 = g[y0*8+x0], v01 = g[y0*8+x1], v10 = g[y1*8+x0], v11 = g[y1*8+x1];
        op[pix] = (1.f-wy)*((1.f-wx)*v00 + wx*v01) + wy*((1.f-wx)*v10 + wx*v11);
    }
}

// ---------------- launcher --------------------------------------------------
extern "C" void kernel_launch(void* const* d_in, const int* in_sizes, int n_in,
                              void* d_out, int out_size) {
    const float* rgb  = (const float*)d_in[0];
    const float* ir   = (const float*)d_in[1];
    const float* pos  = (const float*)d_in[2];
    const float* c1w  = (const float*)d_in[3];
    const float* c2w  = (const float*)d_in[4];
    const float* ln1w = (const float*)d_in[5];
    const float* ln1b = (const float*)d_in[6];
    const float* Wq   = (const float*)d_in[7];
    const float* bq   = (const float*)d_in[8];
    const float* Wk   = (const float*)d_in[9];
    const float* bk   = (const float*)d_in[10];
    const float* Wv   = (const float*)d_in[11];
    const float* bv   = (const float*)d_in[12];
    const float* Wo   = (const float*)d_in[13];
    const float* bo   = (const float*)d_in[14];
    const float* ln2w = (const float*)d_in[15];
    const float* ln2b = (const float*)d_in[16];
    const float* W1   = (const float*)d_in[17];
    const float* b1   = (const float*)d_in[18];
    const float* W2   = (const float*)d_in[19];
    const float* b2   = (const float*)d_in[20];
    const float* lnfw = (const float*)d_in[21];
    const float* lnfb = (const float*)d_in[22];
    float* out = (float*)d_out;

    float *p_x, *p_ln, *p_q, *p_k, *p_v, *p_o, *p_h;
    cudaGetSymbolAddress((void**)&p_x,  g_x);
    cudaGetSymbolAddress((void**)&p_ln, g_ln);
    cudaGetSymbolAddress((void**)&p_q,  g_q);
    cudaGetSymbolAddress((void**)&p_k,  g_k);
    cudaGetSymbolAddress((void**)&p_v,  g_v);
    cudaGetSymbolAddress((void**)&p_o,  g_o);
    cudaGetSymbolAddress((void**)&p_h,  g_h);

    const int ATTN_SMEM = (128*72 + 2*128*68) * 4;  // 106496 B
    cudaFuncSetAttribute(attn_kernel, cudaFuncAttributeMaxDynamicSharedMemorySize, ATTN_SMEM);

    pool_hp_kernel<<<dim3(DMODEL, BSZ, 2), 256>>>(rgb, ir);
    conv1_kernel<<<dim3(BSZ, 4), 512>>>(c1w);
    loss_kernel<<<1, 512>>>(out + (size_t)2*BSZ*512*1024);
    buildx_kernel<<<dim3(SEQL, BSZ), 512>>>(pos, c2w);

    dim3 g512(512/128, NTOK/128);    // (4,32)
    dim3 g2048(2048/128, NTOK/128);  // (16,32)

    for (int l = 0; l < NLAYER; l++) {
        size_t wOff = (size_t)l*512*512, bOff = (size_t)l*512;
        size_t w1Off = (size_t)l*512*2048, b1Off = (size_t)l*2048;
        ln_kernel<<<NTOK, 128>>>(p_x, p_ln, ln1w + bOff, ln1b + bOff);
        gemm_tf32<0><<<g512, 256>>>(p_ln, Wq + wOff, bq + bOff, nullptr, p_q, NTOK, 512, 512);
        gemm_tf32<0><<<g512, 256>>>(p_ln, Wk + wOff, bk + bOff, nullptr, p_k, NTOK, 512, 512);
        gemm_tf32<0><<<g512, 256>>>(p_ln, Wv + wOff, bv + bOff, nullptr, p_v, NTOK, 512, 512);
        attn_kernel<<<BSZ*NHEAD, 256, ATTN_SMEM>>>();
        gemm_tf32<2><<<g512, 256>>>(p_o, Wo + wOff, bo + bOff, p_x, p_x, NTOK, 512, 512);
        ln_kernel<<<NTOK, 128>>>(p_x, p_ln, ln2w + bOff, ln2b + bOff);
        gemm_tf32<1><<<g2048, 256>>>(p_ln, W1 + w1Off, b1 + b1Off, nullptr, p_h, NTOK, 2048, 512);
        gemm_tf32<2><<<g512, 256>>>(p_h, W2 + w1Off, b2 + bOff, p_x, p_x, NTOK, 512, 2048);
    }
    ln_kernel<<<NTOK, 128>>>(p_x, p_ln, lnfw, lnfb);
    upsample_kernel<<<dim3(512, BSZ, 2), 256>>>(out);
}